// round 15
// baseline (speedup 1.0000x reference)
#include <cuda_runtime.h>
#include <cuda_fp16.h>
#include <cuda_bf16.h>
#include <math.h>

#define NG    1024
#define CG    16
#define HH    64
#define WWD   64
#define HW    4096
#define NELEM (CG*HW)   // 65536 floats per group

// ---------------- scratch (static device globals: no runtime alloc) ----------
__device__ __nv_bfloat16 g_x3h[(size_t)NG*CG*HW];   // 128MB cache of exp(silu(conv3x3))
__device__ float g_rowsum[NG*CG*HH];
__device__ float g_colpart[NG*4*CG*WWD];
__device__ float g_z3part[NG*4*CG];
__device__ float g_vsumpart[NG*4*CG];
__device__ float g_ah[NG*CG*HH];
__device__ float g_aw[NG*CG*WWD];
__device__ float g_Z3g[NG*CG];
__device__ float g_v3[NG*CG];
__device__ float g_s1part[NG*4*CG];
__device__ float g_sqpart[NG*4*CG];
__device__ float g_z1part[NG*4*CG];

// ---------------- helpers -----------------------------------------------------
__device__ __forceinline__ unsigned smem_u32(const void* p) {
    unsigned a;
    asm("{ .reg .u64 t; cvta.to.shared.u64 t, %1; cvt.u32.u64 %0, t; }"
        : "=r"(a) : "l"(p));
    return a;
}
__device__ __forceinline__ unsigned pack_h2(float a, float b) {
    __half2 h = __floats2half2_rn(a, b);
    return *reinterpret_cast<unsigned*>(&h);
}
__device__ __forceinline__ void mma16816(float* d, const unsigned a[4],
                                         const unsigned b0, const unsigned b1) {
    asm volatile(
        "mma.sync.aligned.m16n8k16.row.col.f32.f16.f16.f32 "
        "{%0,%1,%2,%3}, {%4,%5,%6,%7}, {%8,%9}, {%0,%1,%2,%3};"
        : "+f"(d[0]), "+f"(d[1]), "+f"(d[2]), "+f"(d[3])
        : "r"(a[0]), "r"(a[1]), "r"(a[2]), "r"(a[3]), "r"(b0), "r"(b1));
}
__device__ __forceinline__ float fast_silu(float z) {
    return __fdividef(z, 1.f + __expf(-z));
}
__device__ __forceinline__ float fast_sig(float z) {
    return __fdividef(1.f, 1.f + __expf(-z));
}

// ---------------- K1: conv3x3 via HMMA + silu + sums + exp-cache + Z3 --------
#define SROWS 18
#define SPIX  (SROWS*66)         // 1188
#define A_BYTES (SPIX*32)        // 38016
#define SB_OFF  A_BYTES
#define SB_BYTES (9*2*32*2*4)    // 4608
#define K1_SMEM (A_BYTES + SB_BYTES)

__global__ __launch_bounds__(256, 3) void k1_conv(
    const float* __restrict__ x, const float* __restrict__ w3,
    const float* __restrict__ b3)
{
    extern __shared__ __align__(128) unsigned char sm[];
    __shared__ float s_v[16], s_z[16], s_b3[16];

    const int n = blockIdx.y, s = blockIdx.x, tid = threadIdx.x;
    const int wid = tid >> 5, lane = tid & 31;
    const int r0 = s * 16;
    const float* xn = x + (size_t)n * NELEM;

    if (tid < 16) { s_v[tid] = 0.f; s_z[tid] = 0.f; s_b3[tid] = b3[tid]; }

    // ---- B fragments in mma layout: sB[tap][nh][lane][2] ----
    {
        unsigned* sB = (unsigned*)(sm + SB_OFF);
        for (int idx = tid; idx < 9*2*32; idx += 256) {
            int tap = idx >> 6, nh = (idx >> 5) & 1, l = idx & 31;
            int g2 = l >> 2, t2 = l & 3;
            const float* wb = w3 + ((nh*8 + g2)*16)*9 + tap;
            sB[idx*2    ] = pack_h2(wb[(2*t2  )*9], wb[(2*t2+1)*9]);
            sB[idx*2 + 1] = pack_h2(wb[(2*t2+8)*9], wb[(2*t2+9)*9]);
        }
    }

    // ---- stage A (fp16 pairs, STS.32) + row/col sums (fp32), MLP-batched ----
    {
        const int ci0 = wid * 2;
        const float* xa = xn + (size_t)ci0 * HW;
        const float* xb = xa + HW;
        const int chalf = ci0 >> 3, cb = (ci0 & 7) * 2;
        float cA0 = 0.f, cA1 = 0.f, cB0 = 0.f, cB1 = 0.f;
        #pragma unroll
        for (int rb = 0; rb < SROWS; rb += 6) {
            float a0[6], a1[6], b0[6], b1[6];
            #pragma unroll
            for (int k = 0; k < 6; k++) {
                int gr = r0 - 1 + rb + k;
                a0[k] = a1[k] = b0[k] = b1[k] = 0.f;
                if (gr >= 0 && gr < HH) {
                    a0[k] = xa[gr*WWD + lane];
                    a1[k] = xa[gr*WWD + lane + 32];
                    b0[k] = xb[gr*WWD + lane];
                    b1[k] = xb[gr*WWD + lane + 32];
                }
            }
            #pragma unroll
            for (int k = 0; k < 6; k++) {
                int rs = rb + k;
                int p0 = rs*66 + 1 + lane, p1 = p0 + 32;
                *(unsigned*)(sm + p0*32 + ((chalf ^ ((p0>>2)&1))<<4) + cb) = pack_h2(a0[k], b0[k]);
                *(unsigned*)(sm + p1*32 + ((chalf ^ ((p1>>2)&1))<<4) + cb) = pack_h2(a1[k], b1[k]);
                if (rs >= 1 && rs <= 16) {
                    cA0 += a0[k]; cA1 += a1[k]; cB0 += b0[k]; cB1 += b1[k];
                    float rsA = a0[k] + a1[k], rsB = b0[k] + b1[k];
                    #pragma unroll
                    for (int o = 16; o > 0; o >>= 1) {
                        rsA += __shfl_xor_sync(~0u, rsA, o);
                        rsB += __shfl_xor_sync(~0u, rsB, o);
                    }
                    if (lane == 0) {
                        g_rowsum[(n*CG + ci0    )*HH + r0 + rs - 1] = rsA;
                        g_rowsum[(n*CG + ci0 + 1)*HH + r0 + rs - 1] = rsB;
                    }
                }
            }
        }
        g_colpart[((n*4 + s)*CG + ci0)*WWD + lane]          = cA0;
        g_colpart[((n*4 + s)*CG + ci0)*WWD + lane + 32]     = cA1;
        g_colpart[((n*4 + s)*CG + ci0 + 1)*WWD + lane]      = cB0;
        g_colpart[((n*4 + s)*CG + ci0 + 1)*WWD + lane + 32] = cB1;
        if (lane < SROWS) {
            int pa = lane*66, pb = lane*66 + 65;
            *(unsigned*)(sm + pa*32 + ((chalf ^ ((pa>>2)&1))<<4) + cb) = 0u;
            *(unsigned*)(sm + pb*32 + ((chalf ^ ((pb>>2)&1))<<4) + cb) = 0u;
        }
    }
    __syncthreads();

    const unsigned smbase = smem_u32(sm);
    const unsigned* sB = (const unsigned*)(sm + SB_OFF);
    const int rowl = (lane < 16) ? lane : lane - 16;
    const int ch = lane >> 4;
    const int g = lane >> 2, t = lane & 3;
    const int wlo = wid & 3, whi = wid >> 2;

    float vs[4] = {0.f,0.f,0.f,0.f}, zs[4] = {0.f,0.f,0.f,0.f};
    float bco[4];
    #pragma unroll
    for (int i = 0; i < 4; i++) bco[i] = s_b3[(i>>1)*8 + t*2 + (i&1)];

    #pragma unroll 1
    for (int batch = 0; batch < 2; batch++) {
        const int seg = whi*2 + batch;
        int pixbase[4];
        #pragma unroll
        for (int k = 0; k < 4; k++) {
            const int rs = 1 + wlo + k*4;
            pixbase[k] = rs*66 + seg*16 + rowl - 66;
        }
        float d[4][8];
        #pragma unroll
        for (int k = 0; k < 4; k++)
            #pragma unroll
            for (int j = 0; j < 8; j++) d[k][j] = 0.f;

        #pragma unroll
        for (int tap = 0; tap < 9; tap++) {
            const int dr = tap/3, dw = tap - dr*3;
            const int dlt = dr*66 + dw;
            const int base0 = ((tap*2    )*32 + lane)*2;
            const int base1 = ((tap*2 + 1)*32 + lane)*2;
            const unsigned Br00 = sB[base0], Br01 = sB[base0 + 1];
            const unsigned Br10 = sB[base1], Br11 = sB[base1 + 1];
            #pragma unroll
            for (int k = 0; k < 4; k++) {
                const int pix = pixbase[k] + dlt;
                unsigned addr = smbase + pix*32 + (((ch ^ (pix>>2)) & 1) << 4);
                unsigned a[4];
                asm volatile("ldmatrix.sync.aligned.m8n8.x4.shared.b16 {%0,%1,%2,%3}, [%4];"
                             : "=r"(a[0]), "=r"(a[1]), "=r"(a[2]), "=r"(a[3]) : "r"(addr));
                mma16816(d[k],     a, Br00, Br01);
                mma16816(d[k] + 4, a, Br10, Br11);
            }
        }
        #pragma unroll
        for (int k = 0; k < 4; k++) {
            const int rs = 1 + wlo + k*4;
            const int row = r0 + rs - 1;
            const int wb = seg*16 + g;
            __nv_bfloat16* ob = g_x3h + (size_t)n*NELEM + row*WWD;
            #pragma unroll
            for (int nh = 0; nh < 2; nh++) {
                #pragma unroll
                for (int j = 0; j < 4; j++) {
                    int co = nh*8 + t*2 + (j & 1);
                    int wi = wb + ((j >= 2) ? 8 : 0);
                    float z = d[k][nh*4 + j] + bco[nh*2 + (j & 1)];
                    float sv = fast_silu(z);
                    float ez = __expf(sv);
                    ob[(size_t)co*HW + wi] = __float2bfloat16(ez);
                    vs[nh*2 + (j & 1)] += sv;
                    zs[nh*2 + (j & 1)] += ez;
                }
            }
        }
    }

    #pragma unroll
    for (int i = 0; i < 4; i++) {
        #pragma unroll
        for (int mask = 4; mask <= 16; mask <<= 1) {
            vs[i] += __shfl_xor_sync(~0u, vs[i], mask);
            zs[i] += __shfl_xor_sync(~0u, zs[i], mask);
        }
    }
    if (lane < 4) {
        #pragma unroll
        for (int i = 0; i < 4; i++) {
            int co = (i>>1)*8 + lane*2 + (i&1);
            atomicAdd(&s_v[co], vs[i]);
            atomicAdd(&s_z[co], zs[i]);
        }
    }
    __syncthreads();
    if (tid < 16) {
        g_vsumpart[(n*4 + s)*CG + tid] = s_v[tid];
        g_z3part[(n*4 + s)*CG + tid]   = s_z[tid];
    }
}

// ---------------- K2: small matmuls (y, a_h, a_w) + x3 stat finalize ---------
__global__ __launch_bounds__(128) void k2_small(
    const float* __restrict__ w1, const float* __restrict__ b1,
    const float* __restrict__ wh, const float* __restrict__ bh,
    const float* __restrict__ ww, const float* __restrict__ bw)
{
    __shared__ float W1s[256], Whs[256], Wws[256], b1s[16], bhs[16], bws[16];
    const int n = blockIdx.x, tid = threadIdx.x;

    for (int i = tid; i < 256; i += 128) { W1s[i] = w1[i]; Whs[i] = wh[i]; Wws[i] = ww[i]; }
    if (tid < 16) { b1s[tid] = b1[tid]; bhs[tid] = bh[tid]; bws[tid] = bw[tid]; }
    __syncthreads();

    const int pos = tid;
    float xcol[16];
    if (pos < 64) {
        #pragma unroll
        for (int ci = 0; ci < 16; ci++)
            xcol[ci] = g_rowsum[(n*CG + ci)*HH + pos] * (1.f/64.f);
    } else {
        const int w = pos - 64;
        #pragma unroll
        for (int ci = 0; ci < 16; ci++) {
            float sv = 0.f;
            for (int st = 0; st < 4; st++)
                sv += g_colpart[((n*4 + st)*CG + ci)*WWD + w];
            xcol[ci] = sv * (1.f/64.f);
        }
    }
    float y[16];
    #pragma unroll
    for (int o = 0; o < 16; o++) {
        float t = b1s[o];
        #pragma unroll
        for (int ci = 0; ci < 16; ci++) t = fmaf(W1s[o*16 + ci], xcol[ci], t);
        y[o] = fast_silu(t);
    }
    if (pos < 64) {
        #pragma unroll
        for (int o = 0; o < 16; o++) {
            float t = bhs[o];
            #pragma unroll
            for (int ci = 0; ci < 16; ci++) t = fmaf(Whs[o*16 + ci], y[ci], t);
            g_ah[(n*CG + o)*HH + pos] = fast_sig(t);
        }
    } else {
        const int w = pos - 64;
        #pragma unroll
        for (int o = 0; o < 16; o++) {
            float t = bws[o];
            #pragma unroll
            for (int ci = 0; ci < 16; ci++) t = fmaf(Wws[o*16 + ci], y[ci], t);
            g_aw[(n*CG + o)*WWD + w] = fast_sig(t);
        }
    }
    if (tid < 16) {
        float z = 0.f, vs = 0.f;
        for (int st = 0; st < 4; st++) {
            z  += g_z3part[(n*4 + st)*CG + tid];
            vs += g_vsumpart[(n*4 + st)*CG + tid];
        }
        g_Z3g[n*CG + tid] = z;
        g_v3[n*CG + tid] = vs * (1.f/4096.f);
    }
}

// ---------------- strip prologue: load ah (strip rows) + aw into smem --------
__device__ __forceinline__ void load_gates(float* ahs, float* aws,
                                           int n, int r0, int tid) {
    #pragma unroll
    for (int i = tid; i < 256; i += 256) {
        int c = i >> 4, r = i & 15;
        ahs[i] = g_ah[(n*CG + c)*HH + r0 + r];
    }
    for (int i = tid; i < CG*WWD; i += 256) aws[i] = g_aw[n*CG*WWD + i];
}

// recompute sc[] (and optionally per-channel sums) from pass-A partials
__device__ __forceinline__ void compute_sc(float* s_sc, float* r_cs,
                                           const float* gamma, int n, int tid,
                                           float* s_inv_mu) {
    __shared__ float r_cq[16];
    if (tid < 16) {
        float cs = 0.f, cq = 0.f;
        #pragma unroll
        for (int st = 0; st < 4; st++) {
            cs += g_s1part[(n*4 + st)*CG + tid];
            cq += g_sqpart[(n*4 + st)*CG + tid];
        }
        r_cs[tid] = cs; r_cq[tid] = cq;
    }
    __syncthreads();
    if (tid == 0) {
        float ts = 0.f, tsq = 0.f;
        #pragma unroll
        for (int i = 0; i < 16; i++) { ts += r_cs[i]; tsq += r_cq[i]; }
        float mu  = ts  * (1.f/65536.f);
        float var = tsq * (1.f/65536.f) - mu*mu;
        s_inv_mu[0] = rsqrtf(var + 1e-5f);
        s_inv_mu[1] = mu;
    }
    __syncthreads();
    if (tid < 16) s_sc[tid] = gamma[tid] * s_inv_mu[0];
    __syncthreads();
}

// ---------------- K3: pass-A partials (strip-parallel) -----------------------
__global__ __launch_bounds__(256) void k3_stats(const float* __restrict__ x)
{
    __shared__ float ahs[256], aws[CG*WWD];
    __shared__ float s_sum[16], s_sq[16];
    const int n = blockIdx.y, s = blockIdx.x, tid = threadIdx.x;
    const int r0 = s * 16;

    load_gates(ahs, aws, n, r0, tid);
    if (tid < 16) { s_sum[tid] = 0.f; s_sq[tid] = 0.f; }
    __syncthreads();

    const float* xs = x + (size_t)n*NELEM + r0*WWD;
    #pragma unroll 1
    for (int c = 0; c < 16; c++) {
        float sum = 0.f, sq = 0.f;
        #pragma unroll
        for (int k = 0; k < 4; k++) {
            int p = k*256 + tid;
            float v = xs[(size_t)c*HW + p];
            float m = ahs[c*16 + (p >> 6)] * aws[c*WWD + (p & 63)];
            float x1 = v * m;
            sum += x1;
            sq = fmaf(x1, x1, sq);
        }
        #pragma unroll
        for (int o = 16; o > 0; o >>= 1) {
            sum += __shfl_xor_sync(~0u, sum, o);
            sq  += __shfl_xor_sync(~0u, sq, o);
        }
        if ((tid & 31) == 0) { atomicAdd(&s_sum[c], sum); atomicAdd(&s_sq[c], sq); }
    }
    __syncthreads();
    if (tid < 16) {
        g_s1part[(n*4 + s)*CG + tid] = s_sum[tid];
        g_sqpart[(n*4 + s)*CG + tid] = s_sq[tid];
    }
}

// ---------------- K4: Z1 partials (strip-parallel) ---------------------------
__global__ __launch_bounds__(256) void k4_z1(const float* __restrict__ x,
                                             const float* __restrict__ gamma)
{
    __shared__ float ahs[256], aws[CG*WWD];
    __shared__ float s_sc[16], r_cs[16], s_im[2], s_z1[16];
    const int n = blockIdx.y, s = blockIdx.x, tid = threadIdx.x;
    const int r0 = s * 16;

    load_gates(ahs, aws, n, r0, tid);
    if (tid < 16) s_z1[tid] = 0.f;
    __syncthreads();
    compute_sc(s_sc, r_cs, gamma, n, tid, s_im);

    const float* xs = x + (size_t)n*NELEM + r0*WWD;
    #pragma unroll 1
    for (int c = 0; c < 16; c++) {
        const float sc = s_sc[c];
        float z = 0.f;
        #pragma unroll
        for (int k = 0; k < 4; k++) {
            int p = k*256 + tid;
            float v = xs[(size_t)c*HW + p];
            float m = sc * ahs[c*16 + (p >> 6)] * aws[c*WWD + (p & 63)];
            z += __expf(m * v);
        }
        #pragma unroll
        for (int o = 16; o > 0; o >>= 1) z += __shfl_xor_sync(~0u, z, o);
        if ((tid & 31) == 0) atomicAdd(&s_z1[c], z);
    }
    __syncthreads();
    if (tid < 16) g_z1part[(n*4 + s)*CG + tid] = s_z1[tid];
}

// ---------------- K5: gate + output (strip-parallel) -------------------------
__global__ __launch_bounds__(256) void k5_out(const float* __restrict__ x,
                                              const float* __restrict__ gamma,
                                              const float* __restrict__ beta,
                                              float* __restrict__ out)
{
    __shared__ float ahs[256], aws[CG*WWD];
    __shared__ float s_sc[16], r_cs[16], s_im[2], s_t1[16], s_t3[16];
    const int n = blockIdx.y, s = blockIdx.x, tid = threadIdx.x;
    const int r0 = s * 16;

    load_gates(ahs, aws, n, r0, tid);
    __syncthreads();
    compute_sc(s_sc, r_cs, gamma, n, tid, s_im);
    if (tid < 16) {
        float a = s_sc[tid], mu = s_im[1];
        float v1 = fmaf(a, r_cs[tid]*(1.f/4096.f) - mu, beta[tid]);
        float z1 = 0.f;
        #pragma unroll
        for (int st = 0; st < 4; st++) z1 += g_z1part[(n*4 + st)*CG + tid];
        s_t1[tid] = g_v3[n*CG + tid] / z1;
        s_t3[tid] = v1 / g_Z3g[n*CG + tid];
    }
    __syncthreads();

    const float* xs = x + (size_t)n*NELEM + r0*WWD;
    const __nv_bfloat16* x3s = g_x3h + (size_t)n*NELEM + r0*WWD;
    float* os = out + (size_t)n*NELEM + r0*WWD;

    #pragma unroll 1
    for (int k = 0; k < 4; k++) {
        const int p = k*256 + tid;
        const int r = p >> 6, w = p & 63;
        float xv[16];
        float acc = 0.f;
        #pragma unroll
        for (int c = 0; c < 16; c++) {
            float xx = xs[(size_t)c*HW + p];
            xv[c] = xx;
            float e3 = __bfloat162float(x3s[(size_t)c*HW + p]);
            float m = s_sc[c] * ahs[c*16 + r] * aws[c*WWD + w];
            acc = fmaf(s_t3[c], e3, fmaf(s_t1[c], __expf(m * xx), acc));
        }
        float sgm = fast_sig(acc);
        #pragma unroll
        for (int c = 0; c < 16; c++) os[(size_t)c*HW + p] = xv[c] * sgm;
    }
}

// ---------------- launcher ----------------------------------------------------
extern "C" void kernel_launch(void* const* d_in, const int* in_sizes, int n_in,
                              void* d_out, int out_size)
{
    const float* x     = (const float*)d_in[0];
    const float* w1    = (const float*)d_in[1];
    const float* b1    = (const float*)d_in[2];
    const float* wh    = (const float*)d_in[3];
    const float* bh    = (const float*)d_in[4];
    const float* ww    = (const float*)d_in[5];
    const float* bw    = (const float*)d_in[6];
    const float* w3    = (const float*)d_in[7];
    const float* b3    = (const float*)d_in[8];
    const float* gamma = (const float*)d_in[9];
    const float* beta  = (const float*)d_in[10];
    float* out = (float*)d_out;

    cudaFuncSetAttribute(k1_conv, cudaFuncAttributeMaxDynamicSharedMemorySize, K1_SMEM);

    k1_conv<<<dim3(4, NG), 256, K1_SMEM>>>(x, w3, b3);
    k2_small<<<NG, 128>>>(w1, b1, wh, bh, ww, bw);
    k3_stats<<<dim3(4, NG), 256>>>(x);
    k4_z1<<<dim3(4, NG), 256>>>(x, gamma);
    k5_out<<<dim3(4, NG), 256>>>(x, gamma, beta, out);
}

// round 17
// speedup vs baseline: 1.5068x; 1.5068x over previous
#include <cuda_runtime.h>
#include <cuda_fp16.h>
#include <cuda_bf16.h>
#include <math.h>

#define NG    1024
#define CG    16
#define HH    64
#define WWD   64
#define HW    4096
#define NELEM (CG*HW)   // 65536 floats per group

// ---------------- scratch (static device globals: no runtime alloc) ----------
__device__ __nv_bfloat16 g_x3h[(size_t)NG*CG*HW];   // 128MB cache of exp(silu(conv3x3))
__device__ float g_rowsum[NG*CG*HH];
__device__ float g_colpart[NG*4*CG*WWD];
__device__ float g_z3part[NG*4*CG];
__device__ float g_vsumpart[NG*4*CG];

// ---------------- helpers -----------------------------------------------------
__device__ __forceinline__ unsigned smem_u32(const void* p) {
    unsigned a;
    asm("{ .reg .u64 t; cvta.to.shared.u64 t, %1; cvt.u32.u64 %0, t; }"
        : "=r"(a) : "l"(p));
    return a;
}
__device__ __forceinline__ unsigned pack_h2(float a, float b) {
    __half2 h = __floats2half2_rn(a, b);
    return *reinterpret_cast<unsigned*>(&h);
}
__device__ __forceinline__ void mma16816(float* d, const unsigned a[4],
                                         const unsigned b0, const unsigned b1) {
    asm volatile(
        "mma.sync.aligned.m16n8k16.row.col.f32.f16.f16.f32 "
        "{%0,%1,%2,%3}, {%4,%5,%6,%7}, {%8,%9}, {%0,%1,%2,%3};"
        : "+f"(d[0]), "+f"(d[1]), "+f"(d[2]), "+f"(d[3])
        : "r"(a[0]), "r"(a[1]), "r"(a[2]), "r"(a[3]), "r"(b0), "r"(b1));
}
__device__ __forceinline__ float fast_silu(float z) {
    return __fdividef(z, 1.f + __expf(-z));
}
__device__ __forceinline__ float fast_sig(float z) {
    return __fdividef(1.f, 1.f + __expf(-z));
}

// ---------------- K1: conv3x3 via HMMA + silu + sums + exp-cache + Z3 --------
#define SROWS 18
#define SPIX  (SROWS*66)         // 1188
#define A_BYTES (SPIX*32)        // 38016
#define SB_OFF  A_BYTES
#define SB_BYTES (9*2*32*2*4)    // 4608
#define K1_SMEM (A_BYTES + SB_BYTES)

__global__ __launch_bounds__(256, 3) void k1_conv(
    const float* __restrict__ x, const float* __restrict__ w3,
    const float* __restrict__ b3)
{
    extern __shared__ __align__(128) unsigned char sm[];
    __shared__ float s_v[16], s_z[16], s_b3[16];

    const int n = blockIdx.y, s = blockIdx.x, tid = threadIdx.x;
    const int wid = tid >> 5, lane = tid & 31;
    const int r0 = s * 16;
    const float* xn = x + (size_t)n * NELEM;

    if (tid < 16) { s_v[tid] = 0.f; s_z[tid] = 0.f; s_b3[tid] = b3[tid]; }

    // ---- B fragments in mma layout: sB[tap][nh][lane][2] ----
    {
        unsigned* sB = (unsigned*)(sm + SB_OFF);
        for (int idx = tid; idx < 9*2*32; idx += 256) {
            int tap = idx >> 6, nh = (idx >> 5) & 1, l = idx & 31;
            int g2 = l >> 2, t2 = l & 3;
            const float* wb = w3 + ((nh*8 + g2)*16)*9 + tap;
            sB[idx*2    ] = pack_h2(wb[(2*t2  )*9], wb[(2*t2+1)*9]);
            sB[idx*2 + 1] = pack_h2(wb[(2*t2+8)*9], wb[(2*t2+9)*9]);
        }
    }

    // ---- stage A (fp16 pairs, STS.32) + row/col sums (fp32), MLP-batched ----
    {
        const int ci0 = wid * 2;
        const float* xa = xn + (size_t)ci0 * HW;
        const float* xb = xa + HW;
        const int chalf = ci0 >> 3, cb = (ci0 & 7) * 2;
        float cA0 = 0.f, cA1 = 0.f, cB0 = 0.f, cB1 = 0.f;
        #pragma unroll
        for (int rb = 0; rb < SROWS; rb += 6) {
            float a0[6], a1[6], b0[6], b1[6];
            #pragma unroll
            for (int k = 0; k < 6; k++) {
                int gr = r0 - 1 + rb + k;
                a0[k] = a1[k] = b0[k] = b1[k] = 0.f;
                if (gr >= 0 && gr < HH) {
                    a0[k] = xa[gr*WWD + lane];
                    a1[k] = xa[gr*WWD + lane + 32];
                    b0[k] = xb[gr*WWD + lane];
                    b1[k] = xb[gr*WWD + lane + 32];
                }
            }
            #pragma unroll
            for (int k = 0; k < 6; k++) {
                int rs = rb + k;
                int p0 = rs*66 + 1 + lane, p1 = p0 + 32;
                *(unsigned*)(sm + p0*32 + ((chalf ^ ((p0>>2)&1))<<4) + cb) = pack_h2(a0[k], b0[k]);
                *(unsigned*)(sm + p1*32 + ((chalf ^ ((p1>>2)&1))<<4) + cb) = pack_h2(a1[k], b1[k]);
                if (rs >= 1 && rs <= 16) {
                    cA0 += a0[k]; cA1 += a1[k]; cB0 += b0[k]; cB1 += b1[k];
                    float rsA = a0[k] + a1[k], rsB = b0[k] + b1[k];
                    #pragma unroll
                    for (int o = 16; o > 0; o >>= 1) {
                        rsA += __shfl_xor_sync(~0u, rsA, o);
                        rsB += __shfl_xor_sync(~0u, rsB, o);
                    }
                    if (lane == 0) {
                        g_rowsum[(n*CG + ci0    )*HH + r0 + rs - 1] = rsA;
                        g_rowsum[(n*CG + ci0 + 1)*HH + r0 + rs - 1] = rsB;
                    }
                }
            }
        }
        g_colpart[((n*4 + s)*CG + ci0)*WWD + lane]          = cA0;
        g_colpart[((n*4 + s)*CG + ci0)*WWD + lane + 32]     = cA1;
        g_colpart[((n*4 + s)*CG + ci0 + 1)*WWD + lane]      = cB0;
        g_colpart[((n*4 + s)*CG + ci0 + 1)*WWD + lane + 32] = cB1;
        if (lane < SROWS) {
            int pa = lane*66, pb = lane*66 + 65;
            *(unsigned*)(sm + pa*32 + ((chalf ^ ((pa>>2)&1))<<4) + cb) = 0u;
            *(unsigned*)(sm + pb*32 + ((chalf ^ ((pb>>2)&1))<<4) + cb) = 0u;
        }
    }
    __syncthreads();

    const unsigned smbase = smem_u32(sm);
    const unsigned* sB = (const unsigned*)(sm + SB_OFF);
    const int rowl = (lane < 16) ? lane : lane - 16;
    const int ch = lane >> 4;
    const int g = lane >> 2, t = lane & 3;
    const int wlo = wid & 3, whi = wid >> 2;

    float vs[4] = {0.f,0.f,0.f,0.f}, zs[4] = {0.f,0.f,0.f,0.f};
    float bco[4];
    #pragma unroll
    for (int i = 0; i < 4; i++) bco[i] = s_b3[(i>>1)*8 + t*2 + (i&1)];

    #pragma unroll 1
    for (int batch = 0; batch < 2; batch++) {
        const int seg = whi*2 + batch;
        int pixbase[4];
        #pragma unroll
        for (int k = 0; k < 4; k++) {
            const int rs = 1 + wlo + k*4;
            pixbase[k] = rs*66 + seg*16 + rowl - 66;
        }
        float d[4][8];
        #pragma unroll
        for (int k = 0; k < 4; k++)
            #pragma unroll
            for (int j = 0; j < 8; j++) d[k][j] = 0.f;

        #pragma unroll
        for (int tap = 0; tap < 9; tap++) {
            const int dr = tap/3, dw = tap - dr*3;
            const int dlt = dr*66 + dw;
            const int base0 = ((tap*2    )*32 + lane)*2;
            const int base1 = ((tap*2 + 1)*32 + lane)*2;
            const unsigned Br00 = sB[base0], Br01 = sB[base0 + 1];
            const unsigned Br10 = sB[base1], Br11 = sB[base1 + 1];
            #pragma unroll
            for (int k = 0; k < 4; k++) {
                const int pix = pixbase[k] + dlt;
                unsigned addr = smbase + pix*32 + (((ch ^ (pix>>2)) & 1) << 4);
                unsigned a[4];
                asm volatile("ldmatrix.sync.aligned.m8n8.x4.shared.b16 {%0,%1,%2,%3}, [%4];"
                             : "=r"(a[0]), "=r"(a[1]), "=r"(a[2]), "=r"(a[3]) : "r"(addr));
                mma16816(d[k],     a, Br00, Br01);
                mma16816(d[k] + 4, a, Br10, Br11);
            }
        }
        // epilogue: bias + silu + exp + bf16 store + stats
        #pragma unroll
        for (int k = 0; k < 4; k++) {
            const int rs = 1 + wlo + k*4;
            const int row = r0 + rs - 1;
            const int wb = seg*16 + g;
            __nv_bfloat16* ob = g_x3h + (size_t)n*NELEM + row*WWD;
            #pragma unroll
            for (int nh = 0; nh < 2; nh++) {
                #pragma unroll
                for (int j = 0; j < 4; j++) {
                    int co = nh*8 + t*2 + (j & 1);
                    int wi = wb + ((j >= 2) ? 8 : 0);
                    float z = d[k][nh*4 + j] + bco[nh*2 + (j & 1)];
                    float sv = fast_silu(z);
                    float ez = __expf(sv);
                    ob[(size_t)co*HW + wi] = __float2bfloat16(ez);
                    vs[nh*2 + (j & 1)] += sv;
                    zs[nh*2 + (j & 1)] += ez;
                }
            }
        }
    }

    // ---- stat reduction ----
    #pragma unroll
    for (int i = 0; i < 4; i++) {
        #pragma unroll
        for (int mask = 4; mask <= 16; mask <<= 1) {
            vs[i] += __shfl_xor_sync(~0u, vs[i], mask);
            zs[i] += __shfl_xor_sync(~0u, zs[i], mask);
        }
    }
    if (lane < 4) {
        #pragma unroll
        for (int i = 0; i < 4; i++) {
            int co = (i>>1)*8 + lane*2 + (i&1);
            atomicAdd(&s_v[co], vs[i]);
            atomicAdd(&s_z[co], zs[i]);
        }
    }
    __syncthreads();
    if (tid < 16) {
        g_vsumpart[(n*4 + s)*CG + tid] = s_v[tid];
        g_z3part[(n*4 + s)*CG + tid]   = s_z[tid];
    }
}

// ---------------- K345: k2 prologue + stats + Z1 + gate + output -------------
__global__ __launch_bounds__(512, 2) void k345(
    const float* __restrict__ x,
    const float* __restrict__ w1, const float* __restrict__ b1,
    const float* __restrict__ wh, const float* __restrict__ bh,
    const float* __restrict__ ww, const float* __restrict__ bw,
    const float* __restrict__ gamma, const float* __restrict__ beta,
    float* __restrict__ out)
{
    __shared__ float ahs[CG*HH], aws[CG*WWD];
    __shared__ float W1s[256], Whs[256], Wws[256], b1s[16], bhs[16], bws[16];
    __shared__ float r_s[16], r_sq[16], r_z1[16];
    __shared__ float s_sc[16], s_t1[16], s_t3[16], s_v3[16], s_Z3[16];

    const int n = blockIdx.x, tid = threadIdx.x;   // 512 = 16 warps

    // ---- prologue: weights + K1 stat finalize ----
    for (int i = tid; i < 256; i += 512) { W1s[i] = w1[i]; Whs[i] = wh[i]; Wws[i] = ww[i]; }
    if (tid < 16) {
        b1s[tid] = b1[tid]; bhs[tid] = bh[tid]; bws[tid] = bw[tid];
        float z = 0.f, vsum = 0.f;
        for (int st = 0; st < 4; st++) {
            z    += g_z3part[(n*4 + st)*CG + tid];
            vsum += g_vsumpart[(n*4 + st)*CG + tid];
        }
        s_Z3[tid] = z;
        s_v3[tid] = vsum * (1.f/4096.f);
    }
    __syncthreads();

    // ---- k2 body: pooled-feature MLP -> ah/aw straight into smem ----
    if (tid < 128) {
        const int pos = tid;
        float xcol[16];
        if (pos < 64) {
            #pragma unroll
            for (int ci = 0; ci < 16; ci++)
                xcol[ci] = g_rowsum[(n*CG + ci)*HH + pos] * (1.f/64.f);
        } else {
            const int w = pos - 64;
            #pragma unroll
            for (int ci = 0; ci < 16; ci++) {
                float sv = 0.f;
                for (int st = 0; st < 4; st++)
                    sv += g_colpart[((n*4 + st)*CG + ci)*WWD + w];
                xcol[ci] = sv * (1.f/64.f);
            }
        }
        float y[16];
        #pragma unroll
        for (int o = 0; o < 16; o++) {
            float t = b1s[o];
            #pragma unroll
            for (int ci = 0; ci < 16; ci++) t = fmaf(W1s[o*16 + ci], xcol[ci], t);
            y[o] = fast_silu(t);
        }
        if (pos < 64) {
            #pragma unroll
            for (int o = 0; o < 16; o++) {
                float t = bhs[o];
                #pragma unroll
                for (int ci = 0; ci < 16; ci++) t = fmaf(Whs[o*16 + ci], y[ci], t);
                ahs[o*HH + pos] = fast_sig(t);
            }
        } else {
            const int w = pos - 64;
            #pragma unroll
            for (int o = 0; o < 16; o++) {
                float t = bws[o];
                #pragma unroll
                for (int ci = 0; ci < 16; ci++) t = fmaf(Wws[o*16 + ci], y[ci], t);
                aws[o*WWD + w] = fast_sig(t);
            }
        }
    }
    __syncthreads();

    const int c = tid >> 5, l = tid & 31;
    const float aw0 = aws[c*WWD + l];
    const float aw1 = aws[c*WWD + l + 32];
    const float* xc = x + (size_t)n*NELEM + (size_t)c*HW;

    // ---- pass A: x1 sum / sumsq (2-row batches for MLP) ----
    {
        float sum = 0.f, sq = 0.f;
        #pragma unroll 2
        for (int r = 0; r < HH; r += 2) {
            float xa0 = xc[r*WWD + l],       xa1 = xc[r*WWD + l + 32];
            float xb0 = xc[(r+1)*WWD + l],   xb1 = xc[(r+1)*WWD + l + 32];
            float ha = ahs[c*HH + r], hb = ahs[c*HH + r + 1];
            float x1a = xa0 * (ha * aw0), x1b = xa1 * (ha * aw1);
            float x1c = xb0 * (hb * aw0), x1d = xb1 * (hb * aw1);
            sum += (x1a + x1b) + (x1c + x1d);
            sq = fmaf(x1a, x1a, fmaf(x1b, x1b, fmaf(x1c, x1c, fmaf(x1d, x1d, sq))));
        }
        #pragma unroll
        for (int o = 16; o > 0; o >>= 1) {
            sum += __shfl_xor_sync(~0u, sum, o);
            sq  += __shfl_xor_sync(~0u, sq, o);
        }
        if (l == 0) { r_s[c] = sum; r_sq[c] = sq; }
    }
    __syncthreads();
    if (tid < 16) {
        float ts = 0.f, tsq = 0.f;
        for (int i = 0; i < 16; i++) { ts += r_s[i]; tsq += r_sq[i]; }
        float mu  = ts  * (1.f/65536.f);
        float var = tsq * (1.f/65536.f) - mu*mu;
        float a = gamma[tid] * rsqrtf(var + 1e-5f);
        s_sc[tid] = a;
        r_s[tid] = fmaf(a, r_s[tid]*(1.f/4096.f) - mu, beta[tid]);   // v1
    }
    __syncthreads();

    // ---- pass B: Z1 (no max subtraction; 2-row batches, x hot in L1/L2) ----
    {
        const float sc = s_sc[c];
        const float caw0 = sc * aw0, caw1 = sc * aw1;
        float z1 = 0.f;
        #pragma unroll 2
        for (int r = 0; r < HH; r += 2) {
            float xa0 = xc[r*WWD + l],       xa1 = xc[r*WWD + l + 32];
            float xb0 = xc[(r+1)*WWD + l],   xb1 = xc[(r+1)*WWD + l + 32];
            float ha = ahs[c*HH + r], hb = ahs[c*HH + r + 1];
            z1 += __expf(ha * caw0 * xa0) + __expf(ha * caw1 * xa1)
                + __expf(hb * caw0 * xb0) + __expf(hb * caw1 * xb1);
        }
        #pragma unroll
        for (int o = 16; o > 0; o >>= 1) z1 += __shfl_xor_sync(~0u, z1, o);
        if (l == 0) r_z1[c] = z1;
    }
    __syncthreads();
    if (tid < 16) {
        s_t1[tid] = s_v3[tid] / r_z1[tid];
        s_t3[tid] = r_s[tid] / s_Z3[tid];
    }
    __syncthreads();

    // ---- pass C: gate + output (no xv cache; re-load x, L1-hot) ----
    const float* xg = x + (size_t)n*NELEM;
    const __nv_bfloat16* x3g = &g_x3h[(size_t)n*NELEM];
    float* og = out + (size_t)n*NELEM;

    for (int it = 0; it < 8; it++) {
        const int p = it*512 + tid;
        const int r = p >> 6, w = p & 63;
        float acc = 0.f;
        #pragma unroll
        for (int cc = 0; cc < 16; cc++) {
            float xx = xg[(size_t)cc*HW + p];
            float e3v = __bfloat162float(x3g[(size_t)cc*HW + p]);
            float m = s_sc[cc] * ahs[cc*HH + r] * aws[cc*WWD + w];
            acc = fmaf(s_t3[cc], e3v, fmaf(s_t1[cc], __expf(m * xx), acc));
        }
        float sgm = fast_sig(acc);
        #pragma unroll
        for (int cc = 0; cc < 16; cc++)
            og[(size_t)cc*HW + p] = xg[(size_t)cc*HW + p] * sgm;
    }
}

// ---------------- launcher ----------------------------------------------------
extern "C" void kernel_launch(void* const* d_in, const int* in_sizes, int n_in,
                              void* d_out, int out_size)
{
    const float* x     = (const float*)d_in[0];
    const float* w1    = (const float*)d_in[1];
    const float* b1    = (const float*)d_in[2];
    const float* wh    = (const float*)d_in[3];
    const float* bh    = (const float*)d_in[4];
    const float* ww    = (const float*)d_in[5];
    const float* bw    = (const float*)d_in[6];
    const float* w3    = (const float*)d_in[7];
    const float* b3    = (const float*)d_in[8];
    const float* gamma = (const float*)d_in[9];
    const float* beta  = (const float*)d_in[10];
    float* out = (float*)d_out;

    cudaFuncSetAttribute(k1_conv, cudaFuncAttributeMaxDynamicSharedMemorySize, K1_SMEM);

    k1_conv<<<dim3(4, NG), 256, K1_SMEM>>>(x, w3, b3);
    k345<<<NG, 512>>>(x, w1, b1, wh, bh, ww, bw, gamma, beta, out);
}